// round 4
// baseline (speedup 1.0000x reference)
#include <cuda_runtime.h>

// GraphPyramidPooling — adjacency (d_in[0]) is dead code for the output.
// Live path: per-level sigmoid scores -> exact stable top-k rank -> gather/
// gate/scatter. Levels: 4096 -> 3276 -> 1965 -> 786.
//
// R3: rank+build fused into ONE kernel per level (4 launches total).
// Exact stable comparator via 64-bit keys: key = (bits(score)<<32) | ~index;
// rank(i) = #{j : key_j > key_i}  (strict u64 >). Each block stages ALL keys
// of its level in smem; warps compute final ranks locally and do the build
// (gate/scatter/out + next-level score matvec) in place. No atomics.

#define D   512
#define DV  (D/4)
#define N0  4096
#define K0  3276
#define N1  3276
#define K1  1965
#define N2  1965
#define K2  786
#define NP0 4096   // padded to multiple of 64
#define NP1 3328
#define NP2 1984

typedef unsigned long long u64;
typedef unsigned int u32;

__device__ u64   g_k0[NP0];
__device__ u64   g_k1[NP1];
__device__ u64   g_k2[NP2];
__device__ float g_h1[(size_t)N1 * D];
__device__ float g_h2[(size_t)N2 * D];

__device__ __forceinline__ float warp_sum(float v) {
#pragma unroll
    for (int o = 16; o; o >>= 1) v += __shfl_xor_sync(0xffffffffu, v, o);
    return v;
}
__device__ __forceinline__ float sigmoidf(float x) {
    return 1.0f / (1.0f + expf(-x));
}
__device__ __forceinline__ u64 make_key(float s, int idx) {
    return ((u64)(u32)__float_as_int(s) << 32) | (u32)(~(u32)idx);
}

// Level-0 scores: one warp per row, writes sort key.
__global__ void scores0_kernel(const float* __restrict__ h,
                               const float* __restrict__ W,
                               const float* __restrict__ b) {
    int w    = (blockIdx.x * blockDim.x + threadIdx.x) >> 5;
    int lane = threadIdx.x & 31;
    if (w >= N0) return;
    const float4* hr = (const float4*)h + (size_t)w * DV;
    const float4* w0 = (const float4*)W;
    float acc = 0.f;
#pragma unroll
    for (int i = 0; i < 4; i++) {
        float4 a = __ldg(hr + lane + 32 * i);
        float4 c = __ldg(w0 + lane + 32 * i);
        acc += a.x * c.x + a.y * c.y + a.z * c.z + a.w * c.w;
    }
    acc = warp_sum(acc);
    if (lane == 0) g_k0[w] = make_key(sigmoidf(acc + __ldg(b + 0)), w);
}

// Fused rank + build for one level. Block (256 thr = 8 warps) stages all NN
// keys in smem; each warp owns WI consecutive rows: counts key_j > key_i over
// the whole array (lanes split j, packed warp-reduce), then builds its rows.
template <int LVL, int NN, int NPAD, int KK, int WI>
__global__ void fused_kernel(const float* __restrict__ h,
                             const float* __restrict__ W,
                             const float* __restrict__ b,
                             float* __restrict__ out) {
    __shared__ __align__(16) u64 smk[NPAD];
    const u64* gk = (LVL == 0) ? g_k0 : (LVL == 1) ? g_k1 : g_k2;

    for (int t = threadIdx.x; t < NPAD; t += blockDim.x)
        smk[t] = (t < NN) ? __ldg(gk + t) : 0ULL;   // 0 < every real key
    __syncthreads();

    const int wid  = threadIdx.x >> 5;
    const int lane = threadIdx.x & 31;
    const int ibase = blockIdx.x * (8 * WI) + wid * WI;

    u64 ki[WI];
    int cnt[WI];
#pragma unroll
    for (int t = 0; t < WI; t++) {
        int i = ibase + t;
        ki[t]  = (i < NN) ? smk[i] : ~0ULL;  // max key -> cnt unused
        cnt[t] = 0;
    }

    const ulonglong2* smk2 = (const ulonglong2*)smk;
#pragma unroll 4
    for (int q = lane; q < NPAD / 2; q += 32) {
        ulonglong2 v = smk2[q];
#pragma unroll
        for (int t = 0; t < WI; t++)
            cnt[t] += (int)(v.x > ki[t]) + (int)(v.y > ki[t]);
    }

    int packed = cnt[0];
    if (WI > 1) packed |= cnt[WI > 1 ? 1 : 0] << 16;
#pragma unroll
    for (int o = 16; o; o >>= 1) packed += __shfl_xor_sync(0xffffffffu, packed, o);

#pragma unroll
    for (int t = 0; t < WI; t++) {
        const int i = ibase + t;
        if (i >= NN) continue;
        const int rank = (t == 0) ? (packed & 0xFFFF) : (packed >> 16);
        const float val = __int_as_float((int)(ki[t] >> 32));
        float4* outr = (float4*)out + (size_t)i * DV;

        if (LVL == 0) {
            const float4* hr = (const float4*)h + (size_t)i * DV;
            if (rank < KK) {
                float4*       h1r = (float4*)g_h1 + (size_t)rank * DV;
                const float4* w1  = (const float4*)W + DV;
                float acc = 0.f;
#pragma unroll
                for (int ii = 0; ii < 4; ii++) {
                    float4 a = __ldg(hr + lane + 32 * ii);
                    a.x *= val; a.y *= val; a.z *= val; a.w *= val;
                    outr[lane + 32 * ii] = a;
                    h1r[lane + 32 * ii]  = a;
                    float4 c = __ldg(w1 + lane + 32 * ii);
                    acc += a.x * c.x + a.y * c.y + a.z * c.z + a.w * c.w;
                }
                acc = warp_sum(acc);
                if (lane == 0)
                    g_k1[rank] = make_key(sigmoidf(acc + __ldg(b + 1)), rank);
            } else {
                float4 z = make_float4(0.f, 0.f, 0.f, 0.f);
#pragma unroll
                for (int ii = 0; ii < 4; ii++) outr[lane + 32 * ii] = z;
            }
        } else if (LVL == 1) {
            if (rank >= KK) continue;
            const float4* h1r = (const float4*)g_h1 + (size_t)i * DV;
            float4*       h2r = (float4*)g_h2 + (size_t)rank * DV;
            const float4* w2  = (const float4*)W + 2 * DV;
            float acc = 0.f;
#pragma unroll
            for (int ii = 0; ii < 4; ii++) {
                float4 a = h1r[lane + 32 * ii];
                a.x *= val; a.y *= val; a.z *= val; a.w *= val;
                float4 o = outr[lane + 32 * ii];
                o.x += a.x; o.y += a.y; o.z += a.z; o.w += a.w;
                outr[lane + 32 * ii] = o;
                h2r[lane + 32 * ii]  = a;
                float4 c = __ldg(w2 + lane + 32 * ii);
                acc += a.x * c.x + a.y * c.y + a.z * c.z + a.w * c.w;
            }
            acc = warp_sum(acc);
            if (lane == 0)
                g_k2[rank] = make_key(sigmoidf(acc + __ldg(b + 2)), rank);
        } else {
            if (rank >= KK) continue;
            const float4* h2r = (const float4*)g_h2 + (size_t)i * DV;
#pragma unroll
            for (int ii = 0; ii < 4; ii++) {
                float4 a = h2r[lane + 32 * ii];
                float4 o = outr[lane + 32 * ii];
                o.x += a.x * val; o.y += a.y * val;
                o.z += a.z * val; o.w += a.w * val;
                outr[lane + 32 * ii] = o;
            }
        }
    }
}

extern "C" void kernel_launch(void* const* d_in, const int* in_sizes, int n_in,
                              void* d_out, int out_size) {
    // inputs: [0]=g (UNUSED), [1]=h [4096,512], [2]=W [3,512], [3]=b [3]
    const float* h = (const float*)d_in[1];
    const float* W = (const float*)d_in[2];
    const float* b = (const float*)d_in[3];
    float* out = (float*)d_out;

    scores0_kernel<<<N0 / 8, 256>>>(h, W, b);
    // 16 rows/block -> 256 blocks
    fused_kernel<0, N0, NP0, K0, 2><<<(N0 + 15) / 16, 256>>>(h, W, b, out);
    // 16 rows/block -> 205 blocks
    fused_kernel<1, N1, NP1, K1, 2><<<(N1 + 15) / 16, 256>>>(h, W, b, out);
    // 8 rows/block -> 246 blocks
    fused_kernel<2, N2, NP2, K2, 1><<<(N2 + 7) / 8, 256>>>(h, W, b, out);
}

// round 5
// speedup vs baseline: 1.0795x; 1.0795x over previous
#include <cuda_runtime.h>

// GraphPyramidPooling — adjacency (d_in[0]) is dead code. Live path:
// 3-level sigmoid-score top-k gather/gate/scatter. 4096 -> 3276 -> 1965 -> 786.
//
// R4: separate memory-parallel work from rank logic.
//  A  (1 pass over h): d0,d1,d2 = h_i·{w0,w1,w2}; s0 + sort key0.
//     (scores of deeper levels use s·(h·w) == (h·s)·w up to fp rounding)
//  R0/R1/R2 (tiny): exact stable rank via u64 keys (bits(s)<<32 | ~idx),
//     chaining per-row SCALARS only: gains, source indices, next-level keys.
//  F  (1 thread per float4): out[r] = a0[r]*h[r] + g1[r]*h[src1[r]]
//                                    + g2[r]*h[src2[r]].  Max MLP.

#define D   512
#define DV  (D/4)
#define N0  4096
#define K0  3276
#define N1  3276
#define K1  1965
#define N2  1965
#define K2  786
#define NP0 4096
#define NP1 3328   // 3276 padded to 64
#define NP2 1984   // 1965 padded to 64

typedef unsigned long long u64;
typedef unsigned int u32;

__device__ u64   g_k0[NP0];
__device__ u64   g_k1[NP1];
__device__ u64   g_k2[NP2];
__device__ float g_s0a[N0];
__device__ float g_d1[N0];
__device__ float g_d2[N0];
__device__ float g_a0[N0];
__device__ float g_g1[N0];
__device__ float g_g2[N0];
__device__ int   g_src1[N0];
__device__ int   g_src2[N0];
__device__ int   g_inv0[N1];
__device__ int   g_p2src[N2];
__device__ float g_p2gain[N2];

__device__ __forceinline__ float warp_sum(float v) {
#pragma unroll
    for (int o = 16; o; o >>= 1) v += __shfl_xor_sync(0xffffffffu, v, o);
    return v;
}
__device__ __forceinline__ float sigmoidf(float x) {
    return 1.0f / (1.0f + expf(-x));
}
__device__ __forceinline__ u64 make_key(float s, int idx) {
    return ((u64)(u32)__float_as_int(s) << 32) | (u32)(~(u32)idx);
}
__device__ __forceinline__ float key_score(u64 k) {
    return __int_as_float((int)(k >> 32));
}

// A: one warp per row; 3 simultaneous dot products. Writes s0/key0/d1/d2 and
// zero-inits the tails of the per-level gain/src arrays.
__global__ void pass_a(const float* __restrict__ h,
                       const float* __restrict__ W,
                       const float* __restrict__ b) {
    int w    = (blockIdx.x * blockDim.x + threadIdx.x) >> 5;
    int lane = threadIdx.x & 31;
    if (w >= N0) return;
    const float4* hr = (const float4*)h + (size_t)w * DV;
    const float4* w0 = (const float4*)W;
    const float4* w1 = w0 + DV;
    const float4* w2 = w0 + 2 * DV;
    float a0 = 0.f, a1 = 0.f, a2 = 0.f;
#pragma unroll
    for (int i = 0; i < 4; i++) {
        float4 a  = __ldg(hr + lane + 32 * i);
        float4 c0 = __ldg(w0 + lane + 32 * i);
        float4 c1 = __ldg(w1 + lane + 32 * i);
        float4 c2 = __ldg(w2 + lane + 32 * i);
        a0 += a.x * c0.x + a.y * c0.y + a.z * c0.z + a.w * c0.w;
        a1 += a.x * c1.x + a.y * c1.y + a.z * c1.z + a.w * c1.w;
        a2 += a.x * c2.x + a.y * c2.y + a.z * c2.z + a.w * c2.w;
    }
    a0 = warp_sum(a0); a1 = warp_sum(a1); a2 = warp_sum(a2);
    if (lane == 0) {
        float s0 = sigmoidf(a0 + __ldg(b + 0));
        g_s0a[w] = s0;
        g_k0[w]  = make_key(s0, w);
        g_d1[w]  = a1;
        g_d2[w]  = a2;
        if (w >= N1) { g_g1[w] = 0.f; g_src1[w] = w; }
        if (w >= N2) { g_g2[w] = 0.f; g_src2[w] = w; }
    }
}

// Rank kernel: stages all level keys in smem; warp owns WI rows, lanes split
// the scan; exact stable rank = #{j : key_j > key_i}. Lane 0 then chains the
// per-row scalars for the next level.
template <int LVL, int NN, int NPAD, int KK, int WI>
__global__ void rank_kernel(const float* __restrict__ b) {
    __shared__ __align__(16) u64 smk[NPAD];
    const u64* gk = (LVL == 0) ? g_k0 : (LVL == 1) ? g_k1 : g_k2;

    for (int t = threadIdx.x; t < NPAD; t += blockDim.x)
        smk[t] = (t < NN) ? __ldg(gk + t) : 0ULL;
    __syncthreads();

    const int wid  = threadIdx.x >> 5;
    const int lane = threadIdx.x & 31;
    const int ibase = blockIdx.x * ((int)(blockDim.x >> 5) * WI) + wid * WI;

    u64 ki[WI];
    int cnt[WI];
#pragma unroll
    for (int t = 0; t < WI; t++) {
        int i = ibase + t;
        ki[t]  = (i < NN) ? smk[i] : ~0ULL;
        cnt[t] = 0;
    }
    const ulonglong2* smk2 = (const ulonglong2*)smk;
#pragma unroll 4
    for (int q = lane; q < NPAD / 2; q += 32) {
        ulonglong2 v = smk2[q];
#pragma unroll
        for (int t = 0; t < WI; t++)
            cnt[t] += (int)(v.x > ki[t]) + (int)(v.y > ki[t]);
    }
    int packed = cnt[0];
    if (WI > 1) packed |= cnt[WI - 1] << 16;
#pragma unroll
    for (int o = 16; o; o >>= 1) packed += __shfl_xor_sync(0xffffffffu, packed, o);

    if (lane != 0) return;
#pragma unroll
    for (int t = 0; t < WI; t++) {
        const int i = ibase + t;
        if (i >= NN) continue;
        const int rank = (t == 0) ? (packed & 0xFFFF) : (packed >> 16);
        const bool sel = rank < KK;
        if (LVL == 0) {
            float s0 = key_score(ki[t]);
            g_a0[i] = sel ? s0 : 0.f;
            if (sel) {
                float s1 = sigmoidf(s0 * g_d1[i] + __ldg(b + 1));
                g_k1[rank]  = make_key(s1, rank);
                g_inv0[rank] = i;
            }
        } else if (LVL == 1) {
            int   src = g_inv0[i];           // original row feeding level-1 row i
            float s1  = key_score(ki[t]);
            float gain = g_s0a[src] * s1;
            g_g1[i]   = sel ? gain : 0.f;
            g_src1[i] = src;
            if (sel) {
                float s2 = sigmoidf(gain * g_d2[src] + __ldg(b + 2));
                g_k2[rank]    = make_key(s2, rank);
                g_p2src[rank]  = src;
                g_p2gain[rank] = gain;
            }
        } else {
            float s2 = key_score(ki[t]);
            g_g2[i]   = sel ? g_p2gain[i] * s2 : 0.f;
            g_src2[i] = g_p2src[i];
        }
    }
}

// F: 1 thread per output float4. out[r] = a0*h[r] + g1*h[src1] + g2*h[src2].
__global__ void final_kernel(const float* __restrict__ h,
                             float* __restrict__ out) {
    int tid = blockIdx.x * blockDim.x + threadIdx.x;   // 0 .. N0*DV-1
    int r = tid >> 7;
    int c = tid & 127;
    float a0 = __ldg(g_a0 + r);
    float g1 = __ldg(g_g1 + r);
    float g2 = __ldg(g_g2 + r);
    int   s1 = __ldg(g_src1 + r);
    int   s2 = __ldg(g_src2 + r);
    const float4* h4 = (const float4*)h;
    float4 v0 = __ldg(h4 + (size_t)r  * DV + c);
    float4 v1 = __ldg(h4 + (size_t)s1 * DV + c);
    float4 v2 = __ldg(h4 + (size_t)s2 * DV + c);
    float4 o;
    o.x = a0 * v0.x + g1 * v1.x + g2 * v2.x;
    o.y = a0 * v0.y + g1 * v1.y + g2 * v2.y;
    o.z = a0 * v0.z + g1 * v1.z + g2 * v2.z;
    o.w = a0 * v0.w + g1 * v1.w + g2 * v2.w;
    ((float4*)out)[tid] = o;
}

extern "C" void kernel_launch(void* const* d_in, const int* in_sizes, int n_in,
                              void* d_out, int out_size) {
    // inputs: [0]=g (UNUSED), [1]=h [4096,512], [2]=W [3,512], [3]=b [3]
    const float* h = (const float*)d_in[1];
    const float* W = (const float*)d_in[2];
    const float* b = (const float*)d_in[3];
    float* out = (float*)d_out;

    pass_a<<<N0 / 8, 256>>>(h, W, b);
    rank_kernel<0, N0, NP0, K0, 2><<<(N0 + 15) / 16, 256>>>(b);  // 256 blocks
    rank_kernel<1, N1, NP1, K1, 2><<<(N1 + 15) / 16, 256>>>(b);  // 205 blocks
    rank_kernel<2, N2, NP2, K2, 1><<<(N2 + 7) / 8, 256>>>(b);    // 246 blocks
    final_kernel<<<(N0 * DV) / 256, 256>>>(h, out);              // 2048 blocks
}